// round 2
// baseline (speedup 1.0000x reference)
#include <cuda_runtime.h>
#include <math.h>

#define TT 2048          // sequence length
#define CC 2048          // embed dim
#define HH 16            // heads
#define DD 128           // head dim
#define NBITS 7

// ---------------- scratch (static device globals; no allocation) ----------------
__device__ float g_Qraw[(size_t)TT * CC];
__device__ float g_Kraw[(size_t)TT * CC];
__device__ float g_Vraw[(size_t)TT * CC];
__device__ float g_Qn[(size_t)HH * TT * DD];   // [h][t][d] rope+rmsnorm
__device__ float g_Kn[(size_t)HH * TT * DD];
__device__ float g_Vt[(size_t)CC * TT];        // Vraw transposed: [h*128+d][t]
__device__ float g_S[(size_t)HH * TT * TT];    // scores -> softmax weights (256MB)
__device__ float g_Y[(size_t)TT * CC];         // attention output, [t][h*128+d]
__device__ int   g_qc[HH * TT];
__device__ int   g_kc[HH * TT];

// ---------------- generic 128x128x8 NT sgemm body ----------------
// C[m,n] = sum_k A[m*lda+k] * B[n*ldb+k]; all dims multiples of 128/8.
template <bool CAUSAL_K>
__device__ __forceinline__ void gemm_nt_body(
    const float* __restrict__ A, int lda,
    const float* __restrict__ B, int ldb,
    float* __restrict__ Cp, int ldc, int Kfull)
{
    __shared__ float As[8][132];
    __shared__ float Bs[8][132];

    const int m0 = blockIdx.y * 128;
    const int n0 = blockIdx.x * 128;
    const int kend = CAUSAL_K ? min(Kfull, (int)(blockIdx.y + 1) * 128) : Kfull;

    const int tid = threadIdx.x;
    const int r = tid >> 4;        // 0..15
    const int c = tid & 15;        // 0..15
    const int lrow = tid >> 1;     // 0..127
    const int lk = (tid & 1) * 4;  // 0 or 4

    float acc[8][8];
#pragma unroll
    for (int i = 0; i < 8; i++)
#pragma unroll
        for (int j = 0; j < 8; j++) acc[i][j] = 0.f;

    for (int k0 = 0; k0 < kend; k0 += 8) {
        float4 av = *(const float4*)(A + (size_t)(m0 + lrow) * lda + k0 + lk);
        float4 bv = *(const float4*)(B + (size_t)(n0 + lrow) * ldb + k0 + lk);
        As[lk + 0][lrow] = av.x; As[lk + 1][lrow] = av.y;
        As[lk + 2][lrow] = av.z; As[lk + 3][lrow] = av.w;
        Bs[lk + 0][lrow] = bv.x; Bs[lk + 1][lrow] = bv.y;
        Bs[lk + 2][lrow] = bv.z; Bs[lk + 3][lrow] = bv.w;
        __syncthreads();
#pragma unroll
        for (int kk = 0; kk < 8; kk++) {
            float a[8], b[8];
#pragma unroll
            for (int i = 0; i < 8; i++) a[i] = As[kk][r * 8 + i];
#pragma unroll
            for (int j = 0; j < 8; j++) b[j] = Bs[kk][c * 8 + j];
#pragma unroll
            for (int i = 0; i < 8; i++)
#pragma unroll
                for (int j = 0; j < 8; j++) acc[i][j] = fmaf(a[i], b[j], acc[i][j]);
        }
        __syncthreads();
    }

#pragma unroll
    for (int i = 0; i < 8; i++) {
        float* crow = Cp + (size_t)(m0 + r * 8 + i) * ldc + n0 + c * 8;
#pragma unroll
        for (int j = 0; j < 8; j++) crow[j] = acc[i][j];
    }
}

// ---------------- QKV projection GEMMs ----------------
__global__ __launch_bounds__(256) void k_gemm_qkv(const float* __restrict__ x,
                                                  const float* __restrict__ W,
                                                  int which)
{
    float* dst = (which == 0) ? g_Qraw : (which == 1) ? g_Kraw : g_Vraw;
    gemm_nt_body<false>(x, CC, W, CC, dst, CC, CC);
}

// ---------------- output projection ----------------
__global__ __launch_bounds__(256) void k_gemm_proj(const float* __restrict__ Wproj,
                                                   float* __restrict__ out)
{
    gemm_nt_body<false>(g_Y, CC, Wproj, CC, out, CC, CC);
}

// ---------------- P @ V (causal K-limit per q-tile) ----------------
__global__ __launch_bounds__(256) void k_pv()
{
    int h = blockIdx.z;
    const float* A = g_S + (size_t)h * TT * TT;     // weights [q][j], lda=T
    const float* B = g_Vt + (size_t)h * DD * TT;    // Vt [d][j],     ldb=T
    float* Cp = g_Y + h * DD;                       // Y [q][h*128+d], ldc=C
    gemm_nt_body<true>(A, TT, B, TT, Cp, CC, TT);
}

// ---------------- RoPE + RMS-norm + ultrametric code (warp per (t,h,{q|k})) ----------------
__global__ __launch_bounds__(256) void k_ropenorm(const float* __restrict__ cosb,
                                                  const float* __restrict__ sinb,
                                                  const float* __restrict__ Wdq,
                                                  const float* __restrict__ Wdk)
{
    int warp = (blockIdx.x * blockDim.x + threadIdx.x) >> 5;
    int lane = threadIdx.x & 31;
    int qk = warp >> 15;            // 0 = q, 1 = k   (T*H = 32768 = 2^15)
    int rem = warp & 32767;
    int t = rem >> 4;
    int h = rem & 15;

    const float* src = (qk ? g_Kraw : g_Qraw) + (size_t)t * CC + h * DD;
    const float* Wd = qk ? Wdk : Wdq;

    float v0 = src[lane], v1 = src[lane + 32], v2 = src[lane + 64], v3 = src[lane + 96];
    float c0 = cosb[t * 64 + lane],      s0 = sinb[t * 64 + lane];
    float c1 = cosb[t * 64 + lane + 32], s1 = sinb[t * 64 + lane + 32];

    // rope: first half x1*c + x2*s ; second half -x1*s + x2*c
    float r0 =  v0 * c0 + v2 * s0;
    float r1 =  v1 * c1 + v3 * s1;
    float r2 = -v0 * s0 + v2 * c0;
    float r3 = -v1 * s1 + v3 * c1;

    float ss = r0 * r0 + r1 * r1 + r2 * r2 + r3 * r3;
#pragma unroll
    for (int o = 16; o; o >>= 1) ss += __shfl_xor_sync(0xffffffffu, ss, o);
    float sc = rsqrtf(ss * (1.0f / 128.0f) + 1e-6f);
    r0 *= sc; r1 *= sc; r2 *= sc; r3 *= sc;

    float* dst = (qk ? g_Kn : g_Qn) + ((size_t)h * TT + t) * DD;
    dst[lane] = r0; dst[lane + 32] = r1; dst[lane + 64] = r2; dst[lane + 96] = r3;

    int code = 0;
#pragma unroll
    for (int k = 0; k < NBITS; k++) {
        float z = r0 * Wd[k * DD + lane] + r1 * Wd[k * DD + lane + 32]
                + r2 * Wd[k * DD + lane + 64] + r3 * Wd[k * DD + lane + 96];
#pragma unroll
        for (int o = 16; o; o >>= 1) z += __shfl_xor_sync(0xffffffffu, z, o);
        float sg = 1.0f / (1.0f + expf(-z));
        int bit = (int)floorf(sg * 1.99f);
        code += bit << k;
    }
    if (lane == 0) (qk ? g_kc : g_qc)[h * TT + t] = code;
}

// ---------------- V transpose (2048x2048) ----------------
__global__ void k_transpose()
{
    __shared__ float tile[32][33];
    int x = blockIdx.x * 32 + threadIdx.x;
    int y = blockIdx.y * 32 + threadIdx.y;
#pragma unroll
    for (int i = 0; i < 32; i += 8)
        tile[threadIdx.y + i][threadIdx.x] = g_Vraw[(size_t)(y + i) * CC + x];
    __syncthreads();
    x = blockIdx.y * 32 + threadIdx.x;
    y = blockIdx.x * 32 + threadIdx.y;
#pragma unroll
    for (int i = 0; i < 32; i += 8)
        g_Vt[(size_t)(y + i) * TT + x] = tile[threadIdx.x][threadIdx.y + i];
}

// ---------------- masked scores: S = (Qn Kn^T)/sqrt(D), ultrametric+causal mask ----------------
__global__ __launch_bounds__(256) void k_scores()
{
    if (blockIdx.x > blockIdx.y) return;   // strictly-upper causal blocks never read
    int h = blockIdx.z;

    __shared__ float As[8][132];
    __shared__ float Bs[8][132];

    const float* A = g_Qn + (size_t)h * TT * DD;
    const float* B = g_Kn + (size_t)h * TT * DD;
    float* Sp = g_S + (size_t)h * TT * TT;

    const int m0 = blockIdx.y * 128;
    const int n0 = blockIdx.x * 128;
    const int tid = threadIdx.x;
    const int r = tid >> 4, c = tid & 15;
    const int lrow = tid >> 1, lk = (tid & 1) * 4;

    float acc[8][8];
#pragma unroll
    for (int i = 0; i < 8; i++)
#pragma unroll
        for (int j = 0; j < 8; j++) acc[i][j] = 0.f;

    for (int k0 = 0; k0 < DD; k0 += 8) {
        float4 av = *(const float4*)(A + (size_t)(m0 + lrow) * DD + k0 + lk);
        float4 bv = *(const float4*)(B + (size_t)(n0 + lrow) * DD + k0 + lk);
        As[lk + 0][lrow] = av.x; As[lk + 1][lrow] = av.y;
        As[lk + 2][lrow] = av.z; As[lk + 3][lrow] = av.w;
        Bs[lk + 0][lrow] = bv.x; Bs[lk + 1][lrow] = bv.y;
        Bs[lk + 2][lrow] = bv.z; Bs[lk + 3][lrow] = bv.w;
        __syncthreads();
#pragma unroll
        for (int kk = 0; kk < 8; kk++) {
            float a[8], b[8];
#pragma unroll
            for (int i = 0; i < 8; i++) a[i] = As[kk][r * 8 + i];
#pragma unroll
            for (int j = 0; j < 8; j++) b[j] = Bs[kk][c * 8 + j];
#pragma unroll
            for (int i = 0; i < 8; i++)
#pragma unroll
                for (int j = 0; j < 8; j++) acc[i][j] = fmaf(a[i], b[j], acc[i][j]);
        }
        __syncthreads();
    }

    const float scale = 0.08838834764831845f;  // 1/sqrt(128)
    int qbase = m0 + r * 8;
    int jbase = n0 + c * 8;
    int qcv[8], kcv[8];
#pragma unroll
    for (int i = 0; i < 8; i++) qcv[i] = g_qc[h * TT + qbase + i];
#pragma unroll
    for (int j = 0; j < 8; j++) kcv[j] = g_kc[h * TT + jbase + j];
#pragma unroll
    for (int i = 0; i < 8; i++) {
        float* srow = Sp + (size_t)(qbase + i) * TT + jbase;
#pragma unroll
        for (int j = 0; j < 8; j++) {
            bool valid = (jbase + j <= qbase + i) && (qcv[i] == kcv[j]);
            srow[j] = valid ? acc[i][j] * scale : -1e30f;
        }
    }
}

// ---------------- row softmax (in place, only over the causal block extent) ----------------
// FIX vs round 0: a row can be FULLY masked (diagonal needs qc==kc which uses
// different weights for q and k). Reference zeroes such rows (any_valid). Detect
// m <= -1e29 and write zeros instead of a bogus uniform distribution.
__global__ __launch_bounds__(128) void k_softmax()
{
    int row = blockIdx.x;          // h*T + q
    int h = row >> 11;
    int q = row & 2047;
    float* S = g_S + (size_t)h * TT * TT + (size_t)q * TT;
    int jmax = ((q >> 7) + 1) << 7;   // entries beyond this are never read by PV
    int tid = threadIdx.x;

    __shared__ float smax[4];
    __shared__ float ssum[4];

    float m = -1e30f;
    for (int j = tid; j < jmax; j += 128) m = fmaxf(m, S[j]);
#pragma unroll
    for (int o = 16; o; o >>= 1) m = fmaxf(m, __shfl_xor_sync(0xffffffffu, m, o));
    if ((tid & 31) == 0) smax[tid >> 5] = m;
    __syncthreads();
    m = fmaxf(fmaxf(smax[0], smax[1]), fmaxf(smax[2], smax[3]));

    if (m <= -1e29f) {
        // no valid key for this query: reference outputs zero row
        for (int j = tid; j < jmax; j += 128) S[j] = 0.0f;
        return;
    }

    float e[16];
    float sum = 0.f;
    int cnt = 0;
    for (int j = tid; j < jmax; j += 128) {
        float v = expf(S[j] - m);   // masked (-1e30) -> underflows to exactly 0
        e[cnt++] = v;
        sum += v;
    }
#pragma unroll
    for (int o = 16; o; o >>= 1) sum += __shfl_xor_sync(0xffffffffu, sum, o);
    if ((tid & 31) == 0) ssum[tid >> 5] = sum;
    __syncthreads();
    sum = ssum[0] + ssum[1] + ssum[2] + ssum[3];

    float inv = 1.0f / sum;          // at least one valid entry -> sum >= 1
    cnt = 0;
    for (int j = tid; j < jmax; j += 128) S[j] = e[cnt++] * inv;
}

// ---------------- launch ----------------
extern "C" void kernel_launch(void* const* d_in, const int* in_sizes, int n_in,
                              void* d_out, int out_size)
{
    const float* x     = (const float*)d_in[0];
    const float* cosb  = (const float*)d_in[1];
    const float* sinb  = (const float*)d_in[2];
    const float* Wq    = (const float*)d_in[3];
    const float* Wk    = (const float*)d_in[4];
    const float* Wv    = (const float*)d_in[5];
    const float* Wproj = (const float*)d_in[6];
    const float* Wdq   = (const float*)d_in[7];
    const float* Wdk   = (const float*)d_in[8];
    float* out = (float*)d_out;

    dim3 g16(16, 16);

    k_gemm_qkv<<<g16, 256>>>(x, Wq, 0);
    k_gemm_qkv<<<g16, 256>>>(x, Wk, 1);
    k_gemm_qkv<<<g16, 256>>>(x, Wv, 2);

    k_ropenorm<<<(2 * TT * HH) / 8, 256>>>(cosb, sinb, Wdq, Wdk);
    k_transpose<<<dim3(64, 64), dim3(32, 8)>>>();

    k_scores<<<dim3(16, 16, HH), 256>>>();
    k_softmax<<<HH * TT, 128>>>();
    k_pv<<<dim3(1, 16, HH), 256>>>();

    k_gemm_proj<<<g16, 256>>>(Wproj, out);
}

// round 5
// speedup vs baseline: 1.4111x; 1.4111x over previous
#include <cuda_runtime.h>
#include <math.h>
#include <stdint.h>

#define TT 2048          // sequence length
#define CC 2048          // embed dim
#define HH 16            // heads
#define DD 128           // head dim
#define NBITS 7
#define BK 32            // k-slab for tf32 core
#define SSTRIDE 36       // fp32 smem row stride (tf32 core)
#define FIXCAP 8192

// ---------------- scratch (static device globals; no allocation) ----------------
__device__ float g_Qraw[(size_t)TT * CC];
__device__ float g_Kraw[(size_t)TT * CC];
__device__ float g_Vraw[(size_t)TT * CC];
__device__ float g_Qn[(size_t)HH * TT * DD];   // [h][t][d] rope+rmsnorm
__device__ float g_Kn[(size_t)HH * TT * DD];
__device__ float g_Vt[(size_t)CC * TT];        // Vraw transposed: [h*128+d][t]
__device__ float g_S[(size_t)HH * TT * TT];    // scores -> softmax weights
__device__ float g_Y[(size_t)TT * CC];         // attention output, [t][h*128+d]
__device__ int   g_qc[HH * TT];
__device__ int   g_kc[HH * TT];
__device__ int   g_fixcnt;
__device__ int   g_fixlist[FIXCAP];

// ============================================================
// tf32x3 GEMM core
// ============================================================
__device__ __forceinline__ void split_tf32(float x, uint32_t& hi, uint32_t& lo)
{
    uint32_t h;
    asm("cvt.rna.tf32.f32 %0, %1;" : "=r"(h) : "f"(x));
    float lf = x - __uint_as_float(h);
    uint32_t l;
    asm("cvt.rna.tf32.f32 %0, %1;" : "=r"(l) : "f"(lf));
    hi = h; lo = l;
}

__device__ __forceinline__ void mma8(float d[4], const uint32_t a[4], const uint32_t b[2])
{
    asm volatile(
        "mma.sync.aligned.m16n8k8.row.col.f32.tf32.tf32.f32 "
        "{%0,%1,%2,%3}, {%4,%5,%6,%7}, {%8,%9}, {%0,%1,%2,%3};"
        : "+f"(d[0]), "+f"(d[1]), "+f"(d[2]), "+f"(d[3])
        : "r"(a[0]), "r"(a[1]), "r"(a[2]), "r"(a[3]), "r"(b[0]), "r"(b[1]));
}

__device__ __forceinline__ void ldg_tile(const float* __restrict__ A, int lda,
                                         int m0, int k0, float4 p[4], int tid)
{
#pragma unroll
    for (int i = 0; i < 4; i++) {
        int slot = tid + 256 * i;
        int m = slot >> 3, jj = slot & 7;
        p[i] = *(const float4*)(A + (size_t)(m0 + m) * lda + k0 + 4 * jj);
    }
}
__device__ __forceinline__ void sts_tile(float* s, const float4 p[4], int tid)
{
#pragma unroll
    for (int i = 0; i < 4; i++) {
        int slot = tid + 256 * i;
        int m = slot >> 3, jj = slot & 7;
        *(float4*)(s + m * SSTRIDE + 4 * jj) = p[i];
    }
}

__device__ __forceinline__ void gemm_core(const float* __restrict__ A, int lda,
                                          const float* __restrict__ B, int ldb,
                                          int m0, int n0, int kend,
                                          float acc[2][8][4])
{
    __shared__ float sA[128 * SSTRIDE];
    __shared__ float sB[128 * SSTRIDE];

    const int tid = threadIdx.x;
    const int lane = tid & 31, warp = tid >> 5;
    const int g = lane >> 2, tig = lane & 3;
    const int wm = (warp & 3) * 32, wn = (warp >> 2) * 64;

#pragma unroll
    for (int tm = 0; tm < 2; tm++)
#pragma unroll
        for (int tn = 0; tn < 8; tn++)
#pragma unroll
            for (int e = 0; e < 4; e++) acc[tm][tn][e] = 0.f;

    float4 pa[4], pb[4];
    ldg_tile(A, lda, m0, 0, pa, tid);
    ldg_tile(B, ldb, n0, 0, pb, tid);

    for (int k0 = 0; k0 < kend; k0 += BK) {
        sts_tile(sA, pa, tid);
        sts_tile(sB, pb, tid);
        __syncthreads();
        if (k0 + BK < kend) {
            ldg_tile(A, lda, m0, k0 + BK, pa, tid);
            ldg_tile(B, ldb, n0, k0 + BK, pb, tid);
        }
#pragma unroll
        for (int kk = 0; kk < BK; kk += 8) {
            uint32_t ah[2][4], al[2][4];
#pragma unroll
            for (int tm = 0; tm < 2; tm++) {
                int r0 = wm + 16 * tm + g;
                split_tf32(sA[r0 * SSTRIDE + kk + tig],       ah[tm][0], al[tm][0]);
                split_tf32(sA[(r0 + 8) * SSTRIDE + kk + tig], ah[tm][1], al[tm][1]);
                split_tf32(sA[r0 * SSTRIDE + kk + tig + 4],       ah[tm][2], al[tm][2]);
                split_tf32(sA[(r0 + 8) * SSTRIDE + kk + tig + 4], ah[tm][3], al[tm][3]);
            }
            uint32_t bh[8][2], bl[8][2];
#pragma unroll
            for (int tn = 0; tn < 8; tn++) {
                int c = wn + 8 * tn + g;
                split_tf32(sB[c * SSTRIDE + kk + tig],     bh[tn][0], bl[tn][0]);
                split_tf32(sB[c * SSTRIDE + kk + tig + 4], bh[tn][1], bl[tn][1]);
            }
#pragma unroll
            for (int tm = 0; tm < 2; tm++)
#pragma unroll
                for (int tn = 0; tn < 8; tn++) {
                    mma8(acc[tm][tn], al[tm], bh[tn]);  // lo*hi
                    mma8(acc[tm][tn], ah[tm], bl[tn]);  // hi*lo
                    mma8(acc[tm][tn], ah[tm], bh[tn]);  // hi*hi
                }
        }
        __syncthreads();
    }
}

__device__ __forceinline__ void epi_store(float* __restrict__ C, int ldc,
                                          int m0, int n0, float acc[2][8][4])
{
    const int lane = threadIdx.x & 31, warp = threadIdx.x >> 5;
    const int g = lane >> 2, tig = lane & 3;
    const int wm = (warp & 3) * 32, wn = (warp >> 2) * 64;
#pragma unroll
    for (int tm = 0; tm < 2; tm++)
#pragma unroll
        for (int tn = 0; tn < 8; tn++) {
            int r = m0 + wm + 16 * tm + g;
            int c = n0 + wn + 8 * tn + 2 * tig;
            *(float2*)(C + (size_t)r * ldc + c) = make_float2(acc[tm][tn][0], acc[tm][tn][1]);
            *(float2*)(C + (size_t)(r + 8) * ldc + c) = make_float2(acc[tm][tn][2], acc[tm][tn][3]);
        }
}

// ---------------- QKV projections (tf32x3) ----------------
__global__ __launch_bounds__(256, 1) void k_qkv_tc(const float* __restrict__ x,
                                                   const float* __restrict__ Wq,
                                                   const float* __restrict__ Wk,
                                                   const float* __restrict__ Wv)
{
    const float* B = (blockIdx.z == 0) ? Wq : (blockIdx.z == 1) ? Wk : Wv;
    float* C = (blockIdx.z == 0) ? g_Qraw : (blockIdx.z == 1) ? g_Kraw : g_Vraw;
    float acc[2][8][4];
    gemm_core(x, CC, B, CC, blockIdx.y * 128, blockIdx.x * 128, CC, acc);
    epi_store(C, CC, blockIdx.y * 128, blockIdx.x * 128, acc);
}

// ---------------- output projection ----------------
__global__ __launch_bounds__(256, 1) void k_proj_tc(const float* __restrict__ Wproj,
                                                    float* __restrict__ out)
{
    float acc[2][8][4];
    gemm_core(g_Y, CC, Wproj, CC, blockIdx.y * 128, blockIdx.x * 128, CC, acc);
    epi_store(out, CC, blockIdx.y * 128, blockIdx.x * 128, acc);
}

// ---------------- masked scores ----------------
__global__ __launch_bounds__(256, 1) void k_scores_tc()
{
    if (blockIdx.x > blockIdx.y) return;   // upper-triangular blocks never read
    const int h = blockIdx.z;
    const float* A = g_Qn + (size_t)h * TT * DD;
    const float* B = g_Kn + (size_t)h * TT * DD;
    float* Sp = g_S + (size_t)h * TT * TT;
    const int m0 = blockIdx.y * 128, n0 = blockIdx.x * 128;

    float acc[2][8][4];
    gemm_core(A, DD, B, DD, m0, n0, DD, acc);

    const float scale = 0.08838834764831845f;  // 1/sqrt(128)
    const int lane = threadIdx.x & 31, warp = threadIdx.x >> 5;
    const int g = lane >> 2, tig = lane & 3;
    const int wm = (warp & 3) * 32, wn = (warp >> 2) * 64;
#pragma unroll
    for (int tm = 0; tm < 2; tm++) {
        int r = m0 + wm + 16 * tm + g;
        int qc0 = g_qc[h * TT + r];
        int qc1 = g_qc[h * TT + r + 8];
#pragma unroll
        for (int tn = 0; tn < 8; tn++) {
            int c = n0 + wn + 8 * tn + 2 * tig;
            int kc0 = g_kc[h * TT + c];
            int kc1 = g_kc[h * TT + c + 1];
            float v00 = (c     <= r     && qc0 == kc0) ? acc[tm][tn][0] * scale : -1e30f;
            float v01 = (c + 1 <= r     && qc0 == kc1) ? acc[tm][tn][1] * scale : -1e30f;
            float v10 = (c     <= r + 8 && qc1 == kc0) ? acc[tm][tn][2] * scale : -1e30f;
            float v11 = (c + 1 <= r + 8 && qc1 == kc1) ? acc[tm][tn][3] * scale : -1e30f;
            *(float2*)(Sp + (size_t)r * TT + c) = make_float2(v00, v01);
            *(float2*)(Sp + (size_t)(r + 8) * TT + c) = make_float2(v10, v11);
        }
    }
}

// ---------------- P @ V ----------------
__global__ __launch_bounds__(256, 1) void k_pv_tc()
{
    const int h = blockIdx.z;
    const float* A = g_S + (size_t)h * TT * TT;   // weights [q][j], lda=T
    const float* B = g_Vt + (size_t)h * DD * TT;  // Vt [d][j], ldb=T
    float* C = g_Y + h * DD;                      // [q][h*128+d], ldc=C
    const int m0 = blockIdx.y * 128;
    const int kend = (blockIdx.y + 1) * 128;      // causal extent

    float acc[2][8][4];
    gemm_core(A, TT, B, TT, m0, 0, kend, acc);
    epi_store(C, CC, m0, 0, acc);
}

// ---------------- worklist counter zero ----------------
__global__ void k_zero_cnt() { g_fixcnt = 0; }

// ---------------- RoPE + RMS-norm + code + margin flagging ----------------
// Source of the arithmetic kept identical to the round-2 version (which passed):
// same expressions, same shuffle reduction order.
__global__ __launch_bounds__(256) void k_ropenorm(const float* __restrict__ cosb,
                                                  const float* __restrict__ sinb,
                                                  const float* __restrict__ Wdq,
                                                  const float* __restrict__ Wdk,
                                                  int append)
{
    int warp = (blockIdx.x * blockDim.x + threadIdx.x) >> 5;
    int lane = threadIdx.x & 31;
    int qk = warp >> 15;            // 0 = q, 1 = k
    int rem = warp & 32767;
    int t = rem >> 4;
    int h = rem & 15;

    const float* src = (qk ? g_Kraw : g_Qraw) + (size_t)t * CC + h * DD;
    const float* Wd = qk ? Wdk : Wdq;

    float v0 = src[lane], v1 = src[lane + 32], v2 = src[lane + 64], v3 = src[lane + 96];
    float c0 = cosb[t * 64 + lane],      s0 = sinb[t * 64 + lane];
    float c1 = cosb[t * 64 + lane + 32], s1 = sinb[t * 64 + lane + 32];

    float r0 =  v0 * c0 + v2 * s0;
    float r1 =  v1 * c1 + v3 * s1;
    float r2 = -v0 * s0 + v2 * c0;
    float r3 = -v1 * s1 + v3 * c1;

    float ss = r0 * r0 + r1 * r1 + r2 * r2 + r3 * r3;
#pragma unroll
    for (int o = 16; o; o >>= 1) ss += __shfl_xor_sync(0xffffffffu, ss, o);
    float sc = rsqrtf(ss * (1.0f / 128.0f) + 1e-6f);
    r0 *= sc; r1 *= sc; r2 *= sc; r3 *= sc;

    float* dst = (qk ? g_Kn : g_Qn) + ((size_t)h * TT + t) * DD;
    dst[lane] = r0; dst[lane + 32] = r1; dst[lane + 64] = r2; dst[lane + 96] = r3;

    int code = 0;
    float margin = 1e30f;
#pragma unroll
    for (int k = 0; k < NBITS; k++) {
        float z = r0 * Wd[k * DD + lane] + r1 * Wd[k * DD + lane + 32]
                + r2 * Wd[k * DD + lane + 64] + r3 * Wd[k * DD + lane + 96];
#pragma unroll
        for (int o = 16; o; o >>= 1) z += __shfl_xor_sync(0xffffffffu, z, o);
        float sg = 1.0f / (1.0f + expf(-z));
        float u = sg * 1.99f;
        int bit = (int)floorf(u);
        margin = fminf(margin, fabsf(u - 1.0f));
        code += bit << k;
    }
    if (lane == 0) {
        (qk ? g_kc : g_qc)[h * TT + t] = code;
        if (append && margin < 1e-4f) {
            int idx = atomicAdd(&g_fixcnt, 1);
            if (idx < FIXCAP) g_fixlist[idx] = (qk << 20) | (h << 16) | t;
        }
    }
}

// ---------------- exact FFMA recompute of flagged raw rows ----------------
// Reproduces the round-2 SGEMM accumulation bitwise: single fp32 accumulator,
// fmaf over k ascending. This is the ordering that provably matched the
// reference's code bits.
__global__ __launch_bounds__(128) void k_fix_raw(const float* __restrict__ x,
                                                 const float* __restrict__ Wq,
                                                 const float* __restrict__ Wk)
{
    int b = blockIdx.x;
    int cnt = g_fixcnt;
    if (cnt > FIXCAP) cnt = FIXCAP;
    if (b >= cnt) return;
    int e = g_fixlist[b];
    int qk = (e >> 20) & 1;
    int h = (e >> 16) & 15;
    int t = e & 0xFFFF;
    const float* W = qk ? Wk : Wq;
    float* dst = (qk ? g_Kraw : g_Qraw) + (size_t)t * CC + h * DD;
    int d = threadIdx.x;  // 0..127
    const float* xr = x + (size_t)t * CC;
    const float* wr = W + (size_t)(h * DD + d) * CC;
    float acc = 0.f;
    for (int k = 0; k < CC; k++) acc = fmaf(xr[k], wr[k], acc);
    dst[d] = acc;
}

// ---------------- V transpose (2048x2048) ----------------
__global__ void k_transpose()
{
    __shared__ float tile[32][33];
    int x = blockIdx.x * 32 + threadIdx.x;
    int y = blockIdx.y * 32 + threadIdx.y;
#pragma unroll
    for (int i = 0; i < 32; i += 8)
        tile[threadIdx.y + i][threadIdx.x] = g_Vraw[(size_t)(y + i) * CC + x];
    __syncthreads();
    x = blockIdx.y * 32 + threadIdx.x;
    y = blockIdx.x * 32 + threadIdx.y;
#pragma unroll
    for (int i = 0; i < 32; i += 8)
        g_Vt[(size_t)(y + i) * TT + x] = tile[threadIdx.x][threadIdx.y + i];
}

// ---------------- row softmax (handles fully-masked rows -> zeros) ----------------
__global__ __launch_bounds__(128) void k_softmax()
{
    int row = blockIdx.x;          // h*T + q
    int h = row >> 11;
    int q = row & 2047;
    float* S = g_S + (size_t)h * TT * TT + (size_t)q * TT;
    int jmax = ((q >> 7) + 1) << 7;
    int tid = threadIdx.x;

    __shared__ float smax[4];
    __shared__ float ssum[4];

    float m = -1e30f;
    for (int j = tid; j < jmax; j += 128) m = fmaxf(m, S[j]);
#pragma unroll
    for (int o = 16; o; o >>= 1) m = fmaxf(m, __shfl_xor_sync(0xffffffffu, m, o));
    if ((tid & 31) == 0) smax[tid >> 5] = m;
    __syncthreads();
    m = fmaxf(fmaxf(smax[0], smax[1]), fmaxf(smax[2], smax[3]));

    if (m <= -1e29f) {
        for (int j = tid; j < jmax; j += 128) S[j] = 0.0f;
        return;
    }

    float e[16];
    float sum = 0.f;
    int cnt = 0;
    for (int j = tid; j < jmax; j += 128) {
        float v = expf(S[j] - m);
        e[cnt++] = v;
        sum += v;
    }
#pragma unroll
    for (int o = 16; o; o >>= 1) sum += __shfl_xor_sync(0xffffffffu, sum, o);
    if ((tid & 31) == 0) ssum[tid >> 5] = sum;
    __syncthreads();
    sum = ssum[0] + ssum[1] + ssum[2] + ssum[3];

    float inv = 1.0f / sum;
    cnt = 0;
    for (int j = tid; j < jmax; j += 128) S[j] = e[cnt++] * inv;
}

// ---------------- launch ----------------
extern "C" void kernel_launch(void* const* d_in, const int* in_sizes, int n_in,
                              void* d_out, int out_size)
{
    const float* x     = (const float*)d_in[0];
    const float* cosb  = (const float*)d_in[1];
    const float* sinb  = (const float*)d_in[2];
    const float* Wq    = (const float*)d_in[3];
    const float* Wk    = (const float*)d_in[4];
    const float* Wv    = (const float*)d_in[5];
    const float* Wproj = (const float*)d_in[6];
    const float* Wdq   = (const float*)d_in[7];
    const float* Wdk   = (const float*)d_in[8];
    float* out = (float*)d_out;

    k_zero_cnt<<<1, 1>>>();
    k_qkv_tc<<<dim3(16, 16, 3), 256>>>(x, Wq, Wk, Wv);

    // pass A: codes + margin flagging
    k_ropenorm<<<(2 * TT * HH) / 8, 256>>>(cosb, sinb, Wdq, Wdk, 1);
    // exact recompute of flagged raw rows (round-2 bitwise ordering)
    k_fix_raw<<<FIXCAP, 128>>>(x, Wq, Wk);
    // pass B: final codes/Qn/Kn from (partially fixed) raw
    k_ropenorm<<<(2 * TT * HH) / 8, 256>>>(cosb, sinb, Wdq, Wdk, 0);

    k_transpose<<<dim3(64, 64), dim3(32, 8)>>>();

    k_scores_tc<<<dim3(16, 16, HH), 256>>>();
    k_softmax<<<HH * TT, 128>>>();
    k_pv_tc<<<dim3(1, 16, HH), 256>>>();

    k_proj_tc<<<dim3(16, 16, 1), 256>>>(Wproj, out);
}